// round 13
// baseline (speedup 1.0000x reference)
#include <cuda_runtime.h>
#include <cuda_fp16.h>
#include <cstdint>
#include <math.h>

#define NB 2
#define NH 12
#define SQ 2048
#define HD 64
#define DM 768

// ---------------- scratch (device globals; no allocations allowed) ----------
__device__ __half g_q[NB * SQ * DM];          // (B,S,H*D) fp16, roped+scaled
__device__ __half g_k[NB * SQ * DM];          // fp16, roped
__device__ __half g_vt[NB * NH * HD * SQ];    // (bh, d, s) fp16
__device__ __half g_attn[NB * SQ * DM];       // fp16 attn out
__device__ __half g_x[NB * SQ * DM];          // fp16 x
__device__ __half g_wq[DM * DM], g_wk[DM * DM], g_wv[DM * DM], g_wo[DM * DM];
__device__ float2 g_tab[SQ * 32];             // (s, half, i) -> (cos, sin)

// ============================ helpers =======================================
__device__ __forceinline__ uint32_t smem_u32(const void* p) {
    uint32_t a;
    asm("{ .reg .u64 t; cvta.to.shared.u64 t, %1; cvt.u32.u64 %0, t; }"
        : "=r"(a) : "l"(p));
    return a;
}
__device__ __forceinline__ uint32_t f22h2(float a, float b) {
    __half2 h = __floats2half2_rn(a, b);
    return *reinterpret_cast<uint32_t*>(&h);
}
__device__ __forceinline__ float2 h2f2(uint32_t h) {
    __half2 hh = *reinterpret_cast<__half2*>(&h);
    return __half22float2(hh);
}
__device__ __forceinline__ uint32_t ex2h2(uint32_t h) {
    uint32_t r;
    asm("ex2.approx.f16x2 %0, %1;" : "=r"(r) : "r"(h));
    return r;
}
__device__ __forceinline__ void ldsm4(uint32_t* r, uint32_t addr) {
    asm volatile("ldmatrix.sync.aligned.m8n8.x4.shared.b16 {%0,%1,%2,%3}, [%4];"
                 : "=r"(r[0]), "=r"(r[1]), "=r"(r[2]), "=r"(r[3]) : "r"(addr));
}
__device__ __forceinline__ void mma16(float* d, const uint32_t* a,
                                      const uint32_t* b) {
    asm volatile(
        "mma.sync.aligned.m16n8k16.row.col.f32.f16.f16.f32 "
        "{%0,%1,%2,%3}, {%4,%5,%6,%7}, {%8,%9}, {%0,%1,%2,%3};"
        : "+f"(d[0]), "+f"(d[1]), "+f"(d[2]), "+f"(d[3])
        : "r"(a[0]), "r"(a[1]), "r"(a[2]), "r"(a[3]), "r"(b[0]), "r"(b[1]));
}
__device__ __forceinline__ void cp16(uint32_t dst, const void* src) {
    asm volatile("cp.async.cg.shared.global [%0], [%1], 16;"
                 :: "r"(dst), "l"(src));
}
#define CP_COMMIT() asm volatile("cp.async.commit_group;" ::: "memory")
#define CP_WAIT(n)  asm volatile("cp.async.wait_group " #n ";" ::: "memory")

// ============================================================================
// Fused prep: x->fp16 | 4 weights->fp16 | rope table, one launch.
// ============================================================================
#define XBLK (NB * SQ * DM / 4 / 256)          // 3072
#define WBLK (DM * DM / 4 / 256)               // 576
#define TBLK (SQ * 32 / 256)                   // 256
__global__ void prep_kernel(const float4* __restrict__ x,
                            const float4* __restrict__ wq,
                            const float4* __restrict__ wk,
                            const float4* __restrict__ wv,
                            const float4* __restrict__ wo,
                            const int* __restrict__ row_ids,
                            const int* __restrict__ col_ids,
                            uint2* __restrict__ dx,
                            uint2* __restrict__ dwq, uint2* __restrict__ dwk,
                            uint2* __restrict__ dwv, uint2* __restrict__ dwo) {
    int blk = blockIdx.x;
    if (blk < XBLK) {
        int i = blk * 256 + threadIdx.x;
        float4 v = x[i];
        dx[i] = make_uint2(f22h2(v.x, v.y), f22h2(v.z, v.w));
    } else if (blk < XBLK + 4 * WBLK) {
        int w = (blk - XBLK) / WBLK;
        int i = ((blk - XBLK) % WBLK) * 256 + threadIdx.x;
        const float4* s = (w == 0) ? wq : (w == 1) ? wk : (w == 2) ? wv : wo;
        uint2* d        = (w == 0) ? dwq : (w == 1) ? dwk : (w == 2) ? dwv : dwo;
        float4 v = s[i];
        d[i] = make_uint2(f22h2(v.x, v.y), f22h2(v.z, v.w));
    } else {
        int idx = (blk - XBLK - 4 * WBLK) * 256 + threadIdx.x;   // < SQ*32
        int s = idx >> 5, p = idx & 31;
        int half = p >> 4, i = p & 15;
        int pos = (half == 0) ? row_ids[s] : col_ids[s];
        float inv = expf(-(float)i * (9.210340371976184f / 16.0f));
        float ang = (float)pos * inv;
        float c, sn;
        sincosf(ang, &sn, &c);
        g_tab[idx] = make_float2(c, sn);
    }
}

// ============================================================================
// fp16 GEMM (FROZEN): CTA tile 64x128, BK=64, 128 thr (4 warps 2x2),
// 3-stage cp.async, 3 CTA/SM, explicit fragment double-buffering.
// OUT32: fp32 C. Else fp16 C with fused 2D-RoPE epilogue (z==0 q * 1/8,
// z==1 k); z==2 writes V transposed fp16 to g_vt.
// ============================================================================
#define GEMM_SMEM 73728

template <int BM, bool OUT32>
__global__ __launch_bounds__(128, 3) void gemm_h(
    const __half* __restrict__ A,
    const __half* __restrict__ W0, const __half* __restrict__ W1,
    const __half* __restrict__ W2,
    void* __restrict__ C0v, void* __restrict__ C1v, void* __restrict__ C2v) {
    const __half* W = (blockIdx.z == 0) ? W0 : (blockIdx.z == 1) ? W1 : W2;
    void* Cv        = (blockIdx.z == 0) ? C0v : (blockIdx.z == 1) ? C1v : C2v;

    constexpr int MT = BM / 32;
    constexpr int ASTAGE = BM * 128;
    constexpr int NCH = DM / 64;

    extern __shared__ __align__(16) char smx[];
    uint32_t smA = smem_u32(smx);
    uint32_t smB = smA + 3 * ASTAGE;

    int tid = threadIdx.x, wid = tid >> 5, lane = tid & 31;
    int m0 = blockIdx.y * BM, n0 = blockIdx.x * 128;
    int wm = wid >> 1, wn = wid & 1;

    int rowAl = wm * (BM / 2) + (lane & 15);
    int cuA   = lane >> 4;
    int rowBl = wn * 64 + ((lane >> 4) * 8) + (lane & 7);
    int cuB   = (lane >> 3) & 1;

    const __half* Ag = A + (size_t)m0 * DM;
    const __half* Wg = W + (size_t)n0 * DM;

#define G_ISSUE(c)                                                          \
    do {                                                                    \
        int _buf = (c) % 3;                                                 \
        uint32_t _sa = smA + _buf * ASTAGE;                                 \
        uint32_t _sb = smB + _buf * 16384;                                  \
        _Pragma("unroll") for (int i = 0; i < BM / 16; i++) {               \
            int idx = tid + i * 128;                                        \
            int r = idx >> 3, u = idx & 7;                                  \
            cp16(_sa + (r * 8 + (u ^ (r & 7))) * 16,                        \
                 Ag + (size_t)r * DM + (c) * 64 + u * 8);                   \
        }                                                                   \
        _Pragma("unroll") for (int i = 0; i < 8; i++) {                     \
            int idx = tid + i * 128;                                        \
            int r = idx >> 3, u = idx & 7;                                  \
            cp16(_sb + (r * 8 + (u ^ (r & 7))) * 16,                        \
                 Wg + (size_t)r * DM + (c) * 64 + u * 8);                   \
        }                                                                   \
    } while (0)

#define LD_FRAG(af, bf, ks)                                                 \
    do {                                                                    \
        _Pragma("unroll") for (int mt = 0; mt < MT; mt++) {                 \
            int rA = rowAl + mt * 16;                                       \
            ldsm4(af[mt], Ab + (rA * 8 + ((2 * (ks) + cuA) ^ (rA & 7))) * 16); \
        }                                                                   \
        _Pragma("unroll") for (int np = 0; np < 4; np++) {                  \
            int rB = rowBl + np * 16;                                       \
            ldsm4(bf[np], Bb + (rB * 8 + ((2 * (ks) + cuB) ^ (rB & 7))) * 16); \
        }                                                                   \
    } while (0)

#define MMA_FRAG(af, bf)                                                    \
    do {                                                                    \
        _Pragma("unroll") for (int mt = 0; mt < MT; mt++)                   \
            _Pragma("unroll") for (int nt = 0; nt < 8; nt++)                \
                mma16(acc[mt][nt], af[mt], &bf[nt >> 1][(nt & 1) * 2]);     \
    } while (0)

    G_ISSUE(0); CP_COMMIT();
    G_ISSUE(1); CP_COMMIT();

    float acc[MT][8][4];
#pragma unroll
    for (int i = 0; i < MT; i++)
#pragma unroll
        for (int j = 0; j < 8; j++)
#pragma unroll
            for (int e = 0; e < 4; e++) acc[i][j][e] = 0.0f;

    uint32_t afA[MT][4], bfA[4][4], afB[MT][4], bfB[4][4];

    for (int c = 0; c < NCH; c++) {
        CP_WAIT(1);
        __syncthreads();
        if (c + 2 < NCH) G_ISSUE(c + 2);
        CP_COMMIT();

        int buf = c % 3;
        uint32_t Ab = smA + buf * ASTAGE;
        uint32_t Bb = smB + buf * 16384;

        LD_FRAG(afA, bfA, 0);
        LD_FRAG(afB, bfB, 1);
        MMA_FRAG(afA, bfA);
        LD_FRAG(afA, bfA, 2);
        MMA_FRAG(afB, bfB);
        LD_FRAG(afB, bfB, 3);
        MMA_FRAG(afA, bfA);
        MMA_FRAG(afB, bfB);
    }

    int g = lane >> 2, tg = lane & 3;
    if (OUT32) {
        float* C = (float*)Cv;
#pragma unroll
        for (int mt = 0; mt < MT; mt++)
#pragma unroll
            for (int nt = 0; nt < 8; nt++)
#pragma unroll
                for (int half = 0; half < 2; half++) {
                    int row = m0 + wm * (BM / 2) + mt * 16 + g + half * 8;
                    int col = n0 + wn * 64 + nt * 8 + tg * 2;
                    float2 v = make_float2(acc[mt][nt][half * 2],
                                           acc[mt][nt][half * 2 + 1]);
                    *(float2*)&C[(size_t)row * DM + col] = v;
                }
    } else if (blockIdx.z == 2) {
#pragma unroll
        for (int mt = 0; mt < MT; mt++)
#pragma unroll
            for (int nt = 0; nt < 8; nt++)
#pragma unroll
                for (int half = 0; half < 2; half++) {
                    int row = m0 + wm * (BM / 2) + mt * 16 + g + half * 8;
                    int b = row >> 11, s = row & (SQ - 1);
                    int col = n0 + wn * 64 + nt * 8 + tg * 2;
                    int h = col >> 6, d = col & 63;
                    size_t base = ((size_t)((b * NH + h) * HD + d)) * SQ + s;
                    g_vt[base]      = __float2half(acc[mt][nt][half * 2]);
                    g_vt[base + SQ] = __float2half(acc[mt][nt][half * 2 + 1]);
                }
    } else {
        float scale = (blockIdx.z == 0) ? 0.125f : 1.0f;
#pragma unroll
        for (int mt = 0; mt < MT; mt++)
#pragma unroll
            for (int e = 0; e < 4; e++) {
                int row = m0 + wm * (BM / 2) + mt * 16 + g + (e >> 1) * 8;
                int s = row & (SQ - 1);
#pragma unroll
                for (int h2 = 0; h2 < 2; h2++) {
                    const float2* tab = g_tab + s * 32 + h2 * 16;
#pragma unroll
                    for (int nt0 = 0; nt0 < 2; nt0++) {
                        int nt = h2 * 4 + nt0;
                        int i = nt0 * 8 + tg * 2 + (e & 1);
                        float2 cs = tab[i];
                        float x1 = acc[mt][nt][e];
                        float x2 = acc[mt][nt + 2][e];
                        acc[mt][nt][e]     = (x1 * cs.x - x2 * cs.y) * scale;
                        acc[mt][nt + 2][e] = (x2 * cs.x + x1 * cs.y) * scale;
                    }
                }
            }
        __half* C = (__half*)Cv;
#pragma unroll
        for (int mt = 0; mt < MT; mt++)
#pragma unroll
            for (int nt = 0; nt < 8; nt++)
#pragma unroll
                for (int half = 0; half < 2; half++) {
                    int row = m0 + wm * (BM / 2) + mt * 16 + g + half * 8;
                    int col = n0 + wn * 64 + nt * 8 + tg * 2;
                    *(uint32_t*)&C[(size_t)row * DM + col] =
                        f22h2(acc[mt][nt][half * 2], acc[mt][nt][half * 2 + 1]);
                }
    }
#undef G_ISSUE
#undef LD_FRAG
#undef MMA_FRAG
}

// ============================================================================
// Flash attention, fp16 mma. CTA: 64q x 128k per iter (two 64-col halves
// sharing ONE softmax pass) — halves barriers/shfl/rescale per unit work.
// Per-warp skip of the fully-masked upper half on boundary tiles.
// smem: Q 8KB + K 2x16KB + V 2x16KB = 72KB. f16x2 exp; V frags hoisted.
// ============================================================================
#define ATT_SMEM 73728
#define L2E 1.44269504f

__global__ __launch_bounds__(128, 2) void attn_h() {
    extern __shared__ __align__(16) char smx[];
    uint32_t Qb    = smem_u32(smx);
    uint32_t Kbase = Qb + 8192;
    uint32_t Vbase = Qb + 40960;

    int tid = threadIdx.x, wid = tid >> 5, lane = tid & 31;
    int bx = blockIdx.x;
    int qt = (SQ / 64 - 1) - bx / (NB * NH);
    int bh = bx % (NB * NH);
    int b = bh / NH, h = bh % NH;

    const __half* Qg  = g_q + ((size_t)(b * SQ + qt * 64)) * DM + h * HD;
    const __half* Kg  = g_k + (size_t)b * SQ * DM + h * HD;
    const __half* Vtg = g_vt + (size_t)bh * HD * SQ;

    int nkt = (qt + 2) >> 1;   // 128-wide tiles covering cols [0, qt*64+63]

    // K tile: 128 rows x 128B (16KB). V tile: 64 d-rows x 256B (16KB).
#define KV_ISSUE(t)                                                         \
    do {                                                                    \
        if ((t) < nkt) {                                                    \
            int _k0 = (t) * 128;                                            \
            uint32_t _ks = Kbase + ((t) & 1) * 16384;                       \
            uint32_t _vs = Vbase + ((t) & 1) * 16384;                       \
            _Pragma("unroll") for (int i = 0; i < 8; i++) {                 \
                int idx = tid + i * 128;                                    \
                int r = idx >> 3, u = idx & 7;                              \
                cp16(_ks + (r * 8 + (u ^ (r & 7))) * 16,                    \
                     Kg + (size_t)(_k0 + r) * DM + u * 8);                  \
            }                                                               \
            _Pragma("unroll") for (int i = 0; i < 8; i++) {                 \
                int idx = tid + i * 128;                                    \
                int r = idx >> 4, u = idx & 15;                             \
                cp16(_vs + (r * 16 + (u ^ (r & 7))) * 16,                   \
                     Vtg + (size_t)r * SQ + _k0 + u * 8);                   \
            }                                                               \
        }                                                                   \
    } while (0)

#define LDV(bv, hh, kb)                                                     \
    do {                                                                    \
        _Pragma("unroll") for (int np = 0; np < 4; np++) {                  \
            int rB = rowBl + np * 16;                                       \
            ldsm4(bv[np], Vb + (rB * 16 + 8 * (hh) +                        \
                                ((2 * (kb) + cuB) ^ (rB & 7))) * 16);       \
        }                                                                   \
    } while (0)

#define PV_MMA(p01, p23, kb, bv)                                            \
    do {                                                                    \
        uint32_t ap[4];                                                     \
        ap[0] = p01[2 * (kb)];                                              \
        ap[1] = p23[2 * (kb)];                                              \
        ap[2] = p01[2 * (kb) + 1];                                          \
        ap[3] = p23[2 * (kb) + 1];                                          \
        _Pragma("unroll") for (int nt = 0; nt < 8; nt++)                    \
            mma16(o[nt], ap, &bv[nt >> 1][(nt & 1) * 2]);                   \
    } while (0)

    KV_ISSUE(0); CP_COMMIT();
#pragma unroll
    for (int i = 0; i < 4; i++) {
        int idx = tid + i * 128;
        int r = idx >> 3, u = idx & 7;
        cp16(Qb + (r * 8 + (u ^ (r & 7))) * 16, Qg + (size_t)r * DM + u * 8);
    }
    CP_COMMIT();
    CP_WAIT(0);
    __syncthreads();

    int rowAl = wid * 16 + (lane & 15);
    int cuA   = lane >> 4;
    int rowBl = ((lane >> 4) * 8) + (lane & 7);
    int cuB   = (lane >> 3) & 1;
    int g = lane >> 2, tg = lane & 3;

    uint32_t aq[4][4];
#pragma unroll
    for (int ks = 0; ks < 4; ks++)
        ldsm4(aq[ks], Qb + (rowAl * 8 + ((2 * ks + cuA) ^ (rowAl & 7))) * 16);

    float o[8][4];
#pragma unroll
    for (int i = 0; i < 8; i++)
#pragma unroll
        for (int e = 0; e < 4; e++) o[i][e] = 0.0f;
    float m0r = -1e30f, m1r = -1e30f, l0 = 0.0f, l1 = 0.0f;

    int qwarp = qt * 64 + wid * 16;

    for (int t = 0; t < nkt; t++) {
        int k0 = t * 128;
        KV_ISSUE(t + 1); CP_COMMIT();

        uint32_t Kb = Kbase + (t & 1) * 16384;
        uint32_t Vb = Vbase + (t & 1) * 16384;

        bool h1act = (k0 + 64 <= qwarp + 15);   // upper half has live cols

        // ---- QK^T both halves ----
        float s0[8][4], s1[8][4];
#pragma unroll
        for (int i = 0; i < 8; i++)
#pragma unroll
            for (int e = 0; e < 4; e++) { s0[i][e] = 0.0f; s1[i][e] = 0.0f; }

#pragma unroll
        for (int ks = 0; ks < 4; ks++) {
            uint32_t bk[4][4];
#pragma unroll
            for (int np = 0; np < 4; np++) {
                int rB = rowBl + np * 16;
                ldsm4(bk[np], Kb + (rB * 8 + ((2 * ks + cuB) ^ (rB & 7))) * 16);
            }
#pragma unroll
            for (int nt = 0; nt < 8; nt++)
                mma16(s0[nt], aq[ks], &bk[nt >> 1][(nt & 1) * 2]);
        }
        if (h1act) {
#pragma unroll
            for (int ks = 0; ks < 4; ks++) {
                uint32_t bk[4][4];
#pragma unroll
                for (int np = 0; np < 4; np++) {
                    int rB = 64 + rowBl + np * 16;
                    ldsm4(bk[np],
                          Kb + (rB * 8 + ((2 * ks + cuB) ^ (rB & 7))) * 16);
                }
#pragma unroll
                for (int nt = 0; nt < 8; nt++)
                    mma16(s1[nt], aq[ks], &bk[nt >> 1][(nt & 1) * 2]);
            }
        }

        // hoist half0 V fragments above softmax
        uint32_t bvA[4][4], bvB[4][4];
        LDV(bvA, 0, 0);
        LDV(bvB, 0, 1);

        // ---- masks (boundary only) ----
        if (k0 + 63 > qwarp) {
#pragma unroll
            for (int nt = 0; nt < 8; nt++)
#pragma unroll
                for (int e = 0; e < 4; e++) {
                    int colg = k0 + nt * 8 + tg * 2 + (e & 1);
                    int rowg = qwarp + g + (e >> 1) * 8;
                    if (colg > rowg) s0[nt][e] = -1e30f;
                }
        }
        if (h1act && (k0 + 127 > qwarp)) {
#pragma unroll
            for (int nt = 0; nt < 8; nt++)
#pragma unroll
                for (int e = 0; e < 4; e++) {
                    int colg = k0 + 64 + nt * 8 + tg * 2 + (e & 1);
                    int rowg = qwarp + g + (e >> 1) * 8;
                    if (colg > rowg) s1[nt][e] = -1e30f;
                }
        }

        // ---- ONE softmax pass over both halves ----
        float rm0 = -1e30f, rm1 = -1e30f;
#pragma unroll
        for (int nt = 0; nt < 8; nt++) {
            rm0 = fmaxf(rm0, fmaxf(s0[nt][0], s0[nt][1]));
            rm1 = fmaxf(rm1, fmaxf(s0[nt][2], s0[nt][3]));
        }
        if (h1act) {
#pragma unroll
            for (int nt = 0; nt < 8; nt++) {
                rm0 = fmaxf(rm0, fmaxf(s1[nt][0], s1[nt][1]));
                rm1 = fmaxf(rm1, fmaxf(s1[nt][2], s1[nt][3]));
            }
        }
        rm0 = fmaxf(rm0, __shfl_xor_sync(0xffffffffu, rm0, 1));
        rm0 = fmaxf(rm0, __shfl_xor_sync(0xffffffffu, rm0, 2));
        rm1 = fmaxf(rm1, __shfl_xor_sync(0xffffffffu, rm1, 1));
        rm1 = fmaxf(rm1, __shfl_xor_sync(0xffffffffu, rm1, 2));
        float mn0 = fmaxf(m0r, rm0), mn1 = fmaxf(m1r, rm1);
        float al0 = __expf(m0r - mn0), al1 = __expf(m1r - mn1);
        m0r = mn0; m1r = mn1;
        float b0 = mn0 * L2E, b1 = mn1 * L2E;

        uint32_t p0a[8], p0b[8], p1a[8], p1b[8];
        float rs0 = 0.0f, rs1 = 0.0f;
#pragma unroll
        for (int nt = 0; nt < 8; nt++) {
            p0a[nt] = ex2h2(f22h2(fmaf(s0[nt][0], L2E, -b0),
                                  fmaf(s0[nt][1], L2E, -b0)));
            p0b[nt] = ex2h2(f22h2(fmaf(s0[nt][2], L2E, -b1),
                                  fmaf(s0[nt][3], L2E, -b1)));
            float2 fa = h2f2(p0a[nt]);
            float2 fb = h2f2(p0b[nt]);
            rs0 += fa.x + fa.y;
            rs1 += fb.x + fb.y;
        }
        if (h1act) {
#pragma unroll
            for (int nt = 0; nt < 8; nt++) {
                p1a[nt] = ex2h2(f22h2(fmaf(s1[nt][0], L2E, -b0),
                                      fmaf(s1[nt][1], L2E, -b0)));
                p1b[nt] = ex2h2(f22h2(fmaf(s1[nt][2], L2E, -b1),
                                      fmaf(s1[nt][3], L2E, -b1)));
                float2 fa = h2f2(p1a[nt]);
                float2 fb = h2f2(p1b[nt]);
                rs0 += fa.x + fa.y;
                rs1 += fb.x + fb.y;
            }
        }
        l0 = l0 * al0 + rs0;
        l1 = l1 * al1 + rs1;
#pragma unroll
        for (int nt = 0; nt < 8; nt++) {
            o[nt][0] *= al0; o[nt][1] *= al0;
            o[nt][2] *= al1; o[nt][3] *= al1;
        }

        // ---- PV half0 (double-buffered V frags), then half1 ----
        PV_MMA(p0a, p0b, 0, bvA);
        LDV(bvA, 0, 2);
        PV_MMA(p0a, p0b, 1, bvB);
        LDV(bvB, 0, 3);
        PV_MMA(p0a, p0b, 2, bvA);
        PV_MMA(p0a, p0b, 3, bvB);
        if (h1act) {
            LDV(bvA, 1, 0);
            LDV(bvB, 1, 1);
            PV_MMA(p1a, p1b, 0, bvA);
            LDV(bvA, 1, 2);
            PV_MMA(p1a, p1b, 1, bvB);
            LDV(bvB, 1, 3);
            PV_MMA(p1a, p1b, 2, bvA);
            PV_MMA(p1a, p1b, 3, bvB);
        }

        CP_WAIT(0);
        __syncthreads();
    }

    l0 += __shfl_xor_sync(0xffffffffu, l0, 1);
    l0 += __shfl_xor_sync(0xffffffffu, l0, 2);
    l1 += __shfl_xor_sync(0xffffffffu, l1, 1);
    l1 += __shfl_xor_sync(0xffffffffu, l1, 2);
    float inv0 = 1.0f / l0, inv1 = 1.0f / l1;

    __half* Og = g_attn + ((size_t)(b * SQ + qt * 64 + wid * 16)) * DM + h * HD;
#pragma unroll
    for (int nt = 0; nt < 8; nt++) {
        int col = nt * 8 + tg * 2;
        *(uint32_t*)&Og[(size_t)g * DM + col] =
            f22h2(o[nt][0] * inv0, o[nt][1] * inv0);
        *(uint32_t*)&Og[(size_t)(g + 8) * DM + col] =
            f22h2(o[nt][2] * inv1, o[nt][3] * inv1);
    }
#undef KV_ISSUE
#undef LDV
#undef PV_MMA
}

// ---------------------------------------------------------------------------
extern "C" void kernel_launch(void* const* d_in, const int* in_sizes, int n_in,
                              void* d_out, int out_size) {
    const float* x  = (const float*)d_in[0];
    const int* row  = (const int*)d_in[1];
    const int* col  = (const int*)d_in[2];
    const float* Wq = (const float*)d_in[3];
    const float* Wk = (const float*)d_in[4];
    const float* Wv = (const float*)d_in[5];
    const float* Wo = (const float*)d_in[6];
    float* out = (float*)d_out;

    void *qp, *kp, *ap, *xp, *wqp, *wkp, *wvp, *wop;
    cudaGetSymbolAddress(&qp, g_q);
    cudaGetSymbolAddress(&kp, g_k);
    cudaGetSymbolAddress(&ap, g_attn);
    cudaGetSymbolAddress(&xp, g_x);
    cudaGetSymbolAddress(&wqp, g_wq);
    cudaGetSymbolAddress(&wkp, g_wk);
    cudaGetSymbolAddress(&wvp, g_wv);
    cudaGetSymbolAddress(&wop, g_wo);

    cudaFuncSetAttribute(gemm_h<64, false>,
                         cudaFuncAttributeMaxDynamicSharedMemorySize, GEMM_SMEM);
    cudaFuncSetAttribute(gemm_h<64, true>,
                         cudaFuncAttributeMaxDynamicSharedMemorySize, GEMM_SMEM);
    cudaFuncSetAttribute(attn_h,
                         cudaFuncAttributeMaxDynamicSharedMemorySize, ATT_SMEM);

    // 0) fused prep: x/W -> fp16, rope table (single launch)
    prep_kernel<<<XBLK + 4 * WBLK + TBLK, 256>>>(
        (const float4*)x, (const float4*)Wq, (const float4*)Wk,
        (const float4*)Wv, (const float4*)Wo, row, col,
        (uint2*)xp, (uint2*)wqp, (uint2*)wkp, (uint2*)wvp, (uint2*)wop);

    // 1) fused QKV projections + RoPE epilogue; z==2 writes V^T to g_vt
    gemm_h<64, false><<<dim3(DM / 128, (NB * SQ) / 64, 3), 128, GEMM_SMEM>>>(
        (const __half*)xp, (const __half*)wqp, (const __half*)wkp,
        (const __half*)wvp, qp, kp, nullptr);

    // 2) flash attention (fp16, heavy-first, 128-wide K tiles)
    attn_h<<<(SQ / 64) * NB * NH, 128, ATT_SMEM>>>();

    // 3) output projection (fp32 out)
    gemm_h<64, true><<<dim3(DM / 128, (NB * SQ) / 64, 1), 128, GEMM_SMEM>>>(
        (const __half*)ap, (const __half*)wop, (const __half*)wop,
        (const __half*)wop, out, out, out);
}

// round 14
// speedup vs baseline: 1.0415x; 1.0415x over previous
#include <cuda_runtime.h>
#include <cuda_fp16.h>
#include <cstdint>
#include <math.h>

#define NB 2
#define NH 12
#define SQ 2048
#define HD 64
#define DM 768

// ---------------- scratch (device globals; no allocations allowed) ----------
__device__ __half g_q[NB * SQ * DM];          // (B,S,H*D) fp16, roped+scaled
__device__ __half g_k[NB * SQ * DM];          // fp16, roped
__device__ __half g_vt[NB * NH * HD * SQ];    // (bh, d, s) fp16
__device__ __half g_attn[NB * SQ * DM];       // fp16 attn out
__device__ __half g_x[NB * SQ * DM];          // fp16 x
__device__ __half g_wq[DM * DM], g_wk[DM * DM], g_wv[DM * DM], g_wo[DM * DM];
__device__ float2 g_tab[SQ * 32];             // (s, half, i) -> (cos, sin)

// ============================ helpers =======================================
__device__ __forceinline__ uint32_t smem_u32(const void* p) {
    uint32_t a;
    asm("{ .reg .u64 t; cvta.to.shared.u64 t, %1; cvt.u32.u64 %0, t; }"
        : "=r"(a) : "l"(p));
    return a;
}
__device__ __forceinline__ uint32_t f22h2(float a, float b) {
    __half2 h = __floats2half2_rn(a, b);
    return *reinterpret_cast<uint32_t*>(&h);
}
__device__ __forceinline__ float2 h2f2(uint32_t h) {
    __half2 hh = *reinterpret_cast<__half2*>(&h);
    return __half22float2(hh);
}
// packed half2 exp2: one MUFU op for two values
__device__ __forceinline__ uint32_t ex2h2(uint32_t h) {
    uint32_t r;
    asm("ex2.approx.f16x2 %0, %1;" : "=r"(r) : "r"(h));
    return r;
}
__device__ __forceinline__ void ldsm4(uint32_t* r, uint32_t addr) {
    asm volatile("ldmatrix.sync.aligned.m8n8.x4.shared.b16 {%0,%1,%2,%3}, [%4];"
                 : "=r"(r[0]), "=r"(r[1]), "=r"(r[2]), "=r"(r[3]) : "r"(addr));
}
__device__ __forceinline__ void mma16(float* d, const uint32_t* a,
                                      const uint32_t* b) {
    asm volatile(
        "mma.sync.aligned.m16n8k16.row.col.f32.f16.f16.f32 "
        "{%0,%1,%2,%3}, {%4,%5,%6,%7}, {%8,%9}, {%0,%1,%2,%3};"
        : "+f"(d[0]), "+f"(d[1]), "+f"(d[2]), "+f"(d[3])
        : "r"(a[0]), "r"(a[1]), "r"(a[2]), "r"(a[3]), "r"(b[0]), "r"(b[1]));
}
__device__ __forceinline__ void cp16(uint32_t dst, const void* src) {
    asm volatile("cp.async.cg.shared.global [%0], [%1], 16;"
                 :: "r"(dst), "l"(src));
}
#define CP_COMMIT() asm volatile("cp.async.commit_group;" ::: "memory")
#define CP_WAIT(n)  asm volatile("cp.async.wait_group " #n ";" ::: "memory")

// ============================================================================
// Fused prep: x->fp16 | 4 weights->fp16 | rope table, one launch.
// 2 float4 per thread (ILP=2, half the blocks vs 1-per-thread).
// ============================================================================
#define XBLK (NB * SQ * DM / 8 / 256)          // 1536 (2 f4/thread)
#define WBLK (DM * DM / 8 / 256)               // 288
#define TBLK (SQ * 32 / 256)                   // 256
__global__ void prep_kernel(const float4* __restrict__ x,
                            const float4* __restrict__ wq,
                            const float4* __restrict__ wk,
                            const float4* __restrict__ wv,
                            const float4* __restrict__ wo,
                            const int* __restrict__ row_ids,
                            const int* __restrict__ col_ids,
                            uint2* __restrict__ dx,
                            uint2* __restrict__ dwq, uint2* __restrict__ dwk,
                            uint2* __restrict__ dwv, uint2* __restrict__ dwo) {
    int blk = blockIdx.x;
    if (blk < XBLK + 4 * WBLK) {
        const float4* s;
        uint2* d;
        int i;
        if (blk < XBLK) {
            s = x; d = dx;
            i = blk * 512 + threadIdx.x * 2;
        } else {
            int w = (blk - XBLK) / WBLK;
            s = (w == 0) ? wq : (w == 1) ? wk : (w == 2) ? wv : wo;
            d = (w == 0) ? dwq : (w == 1) ? dwk : (w == 2) ? dwv : dwo;
            i = ((blk - XBLK) % WBLK) * 512 + threadIdx.x * 2;
        }
        float4 v0 = s[i];
        float4 v1 = s[i + 1];
        d[i]     = make_uint2(f22h2(v0.x, v0.y), f22h2(v0.z, v0.w));
        d[i + 1] = make_uint2(f22h2(v1.x, v1.y), f22h2(v1.z, v1.w));
    } else {
        int idx = (blk - XBLK - 4 * WBLK) * 256 + threadIdx.x;   // < SQ*32
        int s = idx >> 5, p = idx & 31;
        int half = p >> 4, i = p & 15;
        int pos = (half == 0) ? row_ids[s] : col_ids[s];
        float inv = expf(-(float)i * (9.210340371976184f / 16.0f));
        float ang = (float)pos * inv;
        float c, sn;
        sincosf(ang, &sn, &c);
        g_tab[idx] = make_float2(c, sn);
    }
}

// ============================================================================
// fp16 GEMM (FROZEN): CTA tile 64x128, BK=64, 128 thr (4 warps 2x2),
// 3-stage cp.async, 3 CTA/SM, explicit fragment double-buffering.
// OUT32: fp32 C. Else fp16 C with fused 2D-RoPE epilogue (z==0 q * 1/8,
// z==1 k); z==2 writes V transposed fp16 to g_vt.
// ============================================================================
#define GEMM_SMEM 73728

template <int BM, bool OUT32>
__global__ __launch_bounds__(128, 3) void gemm_h(
    const __half* __restrict__ A,
    const __half* __restrict__ W0, const __half* __restrict__ W1,
    const __half* __restrict__ W2,
    void* __restrict__ C0v, void* __restrict__ C1v, void* __restrict__ C2v) {
    const __half* W = (blockIdx.z == 0) ? W0 : (blockIdx.z == 1) ? W1 : W2;
    void* Cv        = (blockIdx.z == 0) ? C0v : (blockIdx.z == 1) ? C1v : C2v;

    constexpr int MT = BM / 32;
    constexpr int ASTAGE = BM * 128;
    constexpr int NCH = DM / 64;

    extern __shared__ __align__(16) char smx[];
    uint32_t smA = smem_u32(smx);
    uint32_t smB = smA + 3 * ASTAGE;

    int tid = threadIdx.x, wid = tid >> 5, lane = tid & 31;
    int m0 = blockIdx.y * BM, n0 = blockIdx.x * 128;
    int wm = wid >> 1, wn = wid & 1;

    int rowAl = wm * (BM / 2) + (lane & 15);
    int cuA   = lane >> 4;
    int rowBl = wn * 64 + ((lane >> 4) * 8) + (lane & 7);
    int cuB   = (lane >> 3) & 1;

    const __half* Ag = A + (size_t)m0 * DM;
    const __half* Wg = W + (size_t)n0 * DM;

#define G_ISSUE(c)                                                          \
    do {                                                                    \
        int _buf = (c) % 3;                                                 \
        uint32_t _sa = smA + _buf * ASTAGE;                                 \
        uint32_t _sb = smB + _buf * 16384;                                  \
        _Pragma("unroll") for (int i = 0; i < BM / 16; i++) {               \
            int idx = tid + i * 128;                                        \
            int r = idx >> 3, u = idx & 7;                                  \
            cp16(_sa + (r * 8 + (u ^ (r & 7))) * 16,                        \
                 Ag + (size_t)r * DM + (c) * 64 + u * 8);                   \
        }                                                                   \
        _Pragma("unroll") for (int i = 0; i < 8; i++) {                     \
            int idx = tid + i * 128;                                        \
            int r = idx >> 3, u = idx & 7;                                  \
            cp16(_sb + (r * 8 + (u ^ (r & 7))) * 16,                        \
                 Wg + (size_t)r * DM + (c) * 64 + u * 8);                   \
        }                                                                   \
    } while (0)

#define LD_FRAG(af, bf, ks)                                                 \
    do {                                                                    \
        _Pragma("unroll") for (int mt = 0; mt < MT; mt++) {                 \
            int rA = rowAl + mt * 16;                                       \
            ldsm4(af[mt], Ab + (rA * 8 + ((2 * (ks) + cuA) ^ (rA & 7))) * 16); \
        }                                                                   \
        _Pragma("unroll") for (int np = 0; np < 4; np++) {                  \
            int rB = rowBl + np * 16;                                       \
            ldsm4(bf[np], Bb + (rB * 8 + ((2 * (ks) + cuB) ^ (rB & 7))) * 16); \
        }                                                                   \
    } while (0)

#define MMA_FRAG(af, bf)                                                    \
    do {                                                                    \
        _Pragma("unroll") for (int mt = 0; mt < MT; mt++)                   \
            _Pragma("unroll") for (int nt = 0; nt < 8; nt++)                \
                mma16(acc[mt][nt], af[mt], &bf[nt >> 1][(nt & 1) * 2]);     \
    } while (0)

    G_ISSUE(0); CP_COMMIT();
    G_ISSUE(1); CP_COMMIT();

    float acc[MT][8][4];
#pragma unroll
    for (int i = 0; i < MT; i++)
#pragma unroll
        for (int j = 0; j < 8; j++)
#pragma unroll
            for (int e = 0; e < 4; e++) acc[i][j][e] = 0.0f;

    uint32_t afA[MT][4], bfA[4][4], afB[MT][4], bfB[4][4];

    for (int c = 0; c < NCH; c++) {
        CP_WAIT(1);
        __syncthreads();
        if (c + 2 < NCH) G_ISSUE(c + 2);
        CP_COMMIT();

        int buf = c % 3;
        uint32_t Ab = smA + buf * ASTAGE;
        uint32_t Bb = smB + buf * 16384;

        LD_FRAG(afA, bfA, 0);
        LD_FRAG(afB, bfB, 1);
        MMA_FRAG(afA, bfA);
        LD_FRAG(afA, bfA, 2);
        MMA_FRAG(afB, bfB);
        LD_FRAG(afB, bfB, 3);
        MMA_FRAG(afA, bfA);
        MMA_FRAG(afB, bfB);
    }

    int g = lane >> 2, tg = lane & 3;
    if (OUT32) {
        float* C = (float*)Cv;
#pragma unroll
        for (int mt = 0; mt < MT; mt++)
#pragma unroll
            for (int nt = 0; nt < 8; nt++)
#pragma unroll
                for (int half = 0; half < 2; half++) {
                    int row = m0 + wm * (BM / 2) + mt * 16 + g + half * 8;
                    int col = n0 + wn * 64 + nt * 8 + tg * 2;
                    float2 v = make_float2(acc[mt][nt][half * 2],
                                           acc[mt][nt][half * 2 + 1]);
                    *(float2*)&C[(size_t)row * DM + col] = v;
                }
    } else if (blockIdx.z == 2) {
#pragma unroll
        for (int mt = 0; mt < MT; mt++)
#pragma unroll
            for (int nt = 0; nt < 8; nt++)
#pragma unroll
                for (int half = 0; half < 2; half++) {
                    int row = m0 + wm * (BM / 2) + mt * 16 + g + half * 8;
                    int b = row >> 11, s = row & (SQ - 1);
                    int col = n0 + wn * 64 + nt * 8 + tg * 2;
                    int h = col >> 6, d = col & 63;
                    size_t base = ((size_t)((b * NH + h) * HD + d)) * SQ + s;
                    g_vt[base]      = __float2half(acc[mt][nt][half * 2]);
                    g_vt[base + SQ] = __float2half(acc[mt][nt][half * 2 + 1]);
                }
    } else {
        float scale = (blockIdx.z == 0) ? 0.125f : 1.0f;
#pragma unroll
        for (int mt = 0; mt < MT; mt++)
#pragma unroll
            for (int e = 0; e < 4; e++) {
                int row = m0 + wm * (BM / 2) + mt * 16 + g + (e >> 1) * 8;
                int s = row & (SQ - 1);
#pragma unroll
                for (int h2 = 0; h2 < 2; h2++) {
                    const float2* tab = g_tab + s * 32 + h2 * 16;
#pragma unroll
                    for (int nt0 = 0; nt0 < 2; nt0++) {
                        int nt = h2 * 4 + nt0;
                        int i = nt0 * 8 + tg * 2 + (e & 1);
                        float2 cs = tab[i];
                        float x1 = acc[mt][nt][e];
                        float x2 = acc[mt][nt + 2][e];
                        acc[mt][nt][e]     = (x1 * cs.x - x2 * cs.y) * scale;
                        acc[mt][nt + 2][e] = (x2 * cs.x + x1 * cs.y) * scale;
                    }
                }
            }
        __half* C = (__half*)Cv;
#pragma unroll
        for (int mt = 0; mt < MT; mt++)
#pragma unroll
            for (int nt = 0; nt < 8; nt++)
#pragma unroll
                for (int half = 0; half < 2; half++) {
                    int row = m0 + wm * (BM / 2) + mt * 16 + g + half * 8;
                    int col = n0 + wn * 64 + nt * 8 + tg * 2;
                    *(uint32_t*)&C[(size_t)row * DM + col] =
                        f22h2(acc[mt][nt][half * 2], acc[mt][nt][half * 2 + 1]);
                }
    }
#undef G_ISSUE
#undef LD_FRAG
#undef MMA_FRAG
}

// ============================================================================
// Flash attention (REVERTED to R12 best): fp16 mma, 64q x 64k, 4 warps,
// 3 CTA/SM; V fragments hoisted above softmax; f16x2 exp (result IS the
// packed P fragment).
// ============================================================================
#define ATT_SMEM 40960
#define L2E 1.44269504f

__global__ __launch_bounds__(128, 3) void attn_h() {
    extern __shared__ __align__(16) char smx[];
    uint32_t Qb    = smem_u32(smx);
    uint32_t Kbase = Qb + 8192;
    uint32_t Vbase = Qb + 24576;

    int tid = threadIdx.x, wid = tid >> 5, lane = tid & 31;
    int bx = blockIdx.x;
    int qt = (SQ / 64 - 1) - bx / (NB * NH);
    int bh = bx % (NB * NH);
    int b = bh / NH, h = bh % NH;

    const __half* Qg  = g_q + ((size_t)(b * SQ + qt * 64)) * DM + h * HD;
    const __half* Kg  = g_k + (size_t)b * SQ * DM + h * HD;
    const __half* Vtg = g_vt + (size_t)bh * HD * SQ;

    int nkt = qt + 1;

#define KV_ISSUE(t)                                                         \
    do {                                                                    \
        if ((t) < nkt) {                                                    \
            int _k0 = (t) * 64;                                             \
            uint32_t _ks = Kbase + ((t) & 1) * 8192;                        \
            uint32_t _vs = Vbase + ((t) & 1) * 8192;                        \
            _Pragma("unroll") for (int i = 0; i < 4; i++) {                 \
                int idx = tid + i * 128;                                    \
                int r = idx >> 3, u = idx & 7;                              \
                cp16(_ks + (r * 8 + (u ^ (r & 7))) * 16,                    \
                     Kg + (size_t)(_k0 + r) * DM + u * 8);                  \
                cp16(_vs + (r * 8 + (u ^ (r & 7))) * 16,                    \
                     Vtg + (size_t)r * SQ + _k0 + u * 8);                   \
            }                                                               \
        }                                                                   \
    } while (0)

#define LDV(bv, kb)                                                         \
    do {                                                                    \
        _Pragma("unroll") for (int np = 0; np < 4; np++) {                  \
            int rB = rowBl + np * 16;                                       \
            ldsm4(bv[np], Vb + (rB * 8 + ((2 * (kb) + cuB) ^ (rB & 7))) * 16); \
        }                                                                   \
    } while (0)

#define PV_MMA(kb, bv)                                                      \
    do {                                                                    \
        uint32_t ap[4];                                                     \
        ap[0] = p01[2 * (kb)];                                              \
        ap[1] = p23[2 * (kb)];                                              \
        ap[2] = p01[2 * (kb) + 1];                                          \
        ap[3] = p23[2 * (kb) + 1];                                          \
        _Pragma("unroll") for (int nt = 0; nt < 8; nt++)                    \
            mma16(o[nt], ap, &bv[nt >> 1][(nt & 1) * 2]);                   \
    } while (0)

    KV_ISSUE(0); CP_COMMIT();
#pragma unroll
    for (int i = 0; i < 4; i++) {
        int idx = tid + i * 128;
        int r = idx >> 3, u = idx & 7;
        cp16(Qb + (r * 8 + (u ^ (r & 7))) * 16, Qg + (size_t)r * DM + u * 8);
    }
    CP_COMMIT();
    CP_WAIT(0);
    __syncthreads();

    int rowAl = wid * 16 + (lane & 15);
    int cuA   = lane >> 4;
    int rowBl = ((lane >> 4) * 8) + (lane & 7);
    int cuB   = (lane >> 3) & 1;
    int g = lane >> 2, tg = lane & 3;

    uint32_t aq[4][4];
#pragma unroll
    for (int ks = 0; ks < 4; ks++)
        ldsm4(aq[ks], Qb + (rowAl * 8 + ((2 * ks + cuA) ^ (rowAl & 7))) * 16);

    float o[8][4];
#pragma unroll
    for (int i = 0; i < 8; i++)
#pragma unroll
        for (int e = 0; e < 4; e++) o[i][e] = 0.0f;
    float m0r = -1e30f, m1r = -1e30f, l0 = 0.0f, l1 = 0.0f;

    int qwarp = qt * 64 + wid * 16;

    for (int t = 0; t < nkt; t++) {
        int k0 = t * 64;
        KV_ISSUE(t + 1); CP_COMMIT();

        uint32_t Kb = Kbase + (t & 1) * 8192;
        uint32_t Vb = Vbase + (t & 1) * 8192;

        float s[8][4];
#pragma unroll
        for (int i = 0; i < 8; i++)
#pragma unroll
            for (int e = 0; e < 4; e++) s[i][e] = 0.0f;

#pragma unroll
        for (int ks = 0; ks < 4; ks++) {
            uint32_t bk[4][4];
#pragma unroll
            for (int np = 0; np < 4; np++) {
                int rB = rowBl + np * 16;
                ldsm4(bk[np], Kb + (rB * 8 + ((2 * ks + cuB) ^ (rB & 7))) * 16);
            }
#pragma unroll
            for (int nt = 0; nt < 8; nt++)
                mma16(s[nt], aq[ks], &bk[nt >> 1][(nt & 1) * 2]);
        }

        // hoist V fragments for kb 0,1 above softmax — latency hidden by exp
        uint32_t bvA[4][4], bvB[4][4];
        LDV(bvA, 0);
        LDV(bvB, 1);

        if (k0 + 63 > qwarp) {
#pragma unroll
            for (int nt = 0; nt < 8; nt++)
#pragma unroll
                for (int e = 0; e < 4; e++) {
                    int colg = k0 + nt * 8 + tg * 2 + (e & 1);
                    int rowg = qwarp + g + (e >> 1) * 8;
                    if (colg > rowg) s[nt][e] = -1e30f;
                }
        }

        float rm0 = -1e30f, rm1 = -1e30f;
#pragma unroll
        for (int nt = 0; nt < 8; nt++) {
            rm0 = fmaxf(rm0, fmaxf(s[nt][0], s[nt][1]));
            rm1 = fmaxf(rm1, fmaxf(s[nt][2], s[nt][3]));
        }
        rm0 = fmaxf(rm0, __shfl_xor_sync(0xffffffffu, rm0, 1));
        rm0 = fmaxf(rm0, __shfl_xor_sync(0xffffffffu, rm0, 2));
        rm1 = fmaxf(rm1, __shfl_xor_sync(0xffffffffu, rm1, 1));
        rm1 = fmaxf(rm1, __shfl_xor_sync(0xffffffffu, rm1, 2));
        float mn0 = fmaxf(m0r, rm0), mn1 = fmaxf(m1r, rm1);
        float al0 = __expf(m0r - mn0), al1 = __expf(m1r - mn1);
        m0r = mn0; m1r = mn1;
        float b0 = mn0 * L2E, b1 = mn1 * L2E;

        // exp in base-2, packed f16x2: 16 MUFU ops instead of 32.
        uint32_t p01[8], p23[8];
        float rs0 = 0.0f, rs1 = 0.0f;
#pragma unroll
        for (int nt = 0; nt < 8; nt++) {
            float t0 = fmaf(s[nt][0], L2E, -b0);
            float t1 = fmaf(s[nt][1], L2E, -b0);
            float t2 = fmaf(s[nt][2], L2E, -b1);
            float t3 = fmaf(s[nt][3], L2E, -b1);
            p01[nt] = ex2h2(f22h2(t0, t1));
            p23[nt] = ex2h2(f22h2(t2, t3));
            float2 f01 = h2f2(p01[nt]);
            float2 f23 = h2f2(p23[nt]);
            rs0 += f01.x + f01.y;
            rs1 += f23.x + f23.y;
        }
        l0 = l0 * al0 + rs0;
        l1 = l1 * al1 + rs1;
#pragma unroll
        for (int nt = 0; nt < 8; nt++) {
            o[nt][0] *= al0; o[nt][1] *= al0;
            o[nt][2] *= al1; o[nt][3] *= al1;
        }

        // PV with double-buffered V fragments
        PV_MMA(0, bvA);
        LDV(bvA, 2);
        PV_MMA(1, bvB);
        LDV(bvB, 3);
        PV_MMA(2, bvA);
        PV_MMA(3, bvB);

        CP_WAIT(0);
        __syncthreads();
    }

    l0 += __shfl_xor_sync(0xffffffffu, l0, 1);
    l0 += __shfl_xor_sync(0xffffffffu, l0, 2);
    l1 += __shfl_xor_sync(0xffffffffu, l1, 1);
    l1 += __shfl_xor_sync(0xffffffffu, l1, 2);
    float inv0 = 1.0f / l0, inv1 = 1.0f / l1;

    __half* Og = g_attn + ((size_t)(b * SQ + qt * 64 + wid * 16)) * DM + h * HD;
#pragma unroll
    for (int nt = 0; nt < 8; nt++) {
        int col = nt * 8 + tg * 2;
        *(uint32_t*)&Og[(size_t)g * DM + col] =
            f22h2(o[nt][0] * inv0, o[nt][1] * inv0);
        *(uint32_t*)&Og[(size_t)(g + 8) * DM + col] =
            f22h2(o[nt][2] * inv1, o[nt][3] * inv1);
    }
#undef KV_ISSUE
#undef LDV
#undef PV_MMA
}

// ---------------------------------------------------------------------------
extern "C" void kernel_launch(void* const* d_in, const int* in_sizes, int n_in,
                              void* d_out, int out_size) {
    const float* x  = (const float*)d_in[0];
    const int* row  = (const int*)d_in[1];
    const int* col  = (const int*)d_in[2];
    const float* Wq = (const float*)d_in[3];
    const float* Wk = (const float*)d_in[4];
    const float* Wv = (const float*)d_in[5];
    const float* Wo = (const float*)d_in[6];
    float* out = (float*)d_out;

    void *qp, *kp, *ap, *xp, *wqp, *wkp, *wvp, *wop;
    cudaGetSymbolAddress(&qp, g_q);
    cudaGetSymbolAddress(&kp, g_k);
    cudaGetSymbolAddress(&ap, g_attn);
    cudaGetSymbolAddress(&xp, g_x);
    cudaGetSymbolAddress(&wqp, g_wq);
    cudaGetSymbolAddress(&wkp, g_wk);
    cudaGetSymbolAddress(&wvp, g_wv);
    cudaGetSymbolAddress(&wop, g_wo);

    cudaFuncSetAttribute(gemm_h<64, false>,
                         cudaFuncAttributeMaxDynamicSharedMemorySize, GEMM_SMEM);
    cudaFuncSetAttribute(gemm_h<64, true>,
                         cudaFuncAttributeMaxDynamicSharedMemorySize, GEMM_SMEM);
    cudaFuncSetAttribute(attn_h,
                         cudaFuncAttributeMaxDynamicSharedMemorySize, ATT_SMEM);

    // 0) fused prep: x/W -> fp16 (2 f4/thread), rope table (single launch)
    prep_kernel<<<XBLK + 4 * WBLK + TBLK, 256>>>(
        (const float4*)x, (const float4*)Wq, (const float4*)Wk,
        (const float4*)Wv, (const float4*)Wo, row, col,
        (uint2*)xp, (uint2*)wqp, (uint2*)wkp, (uint2*)wvp, (uint2*)wop);

    // 1) fused QKV projections + RoPE epilogue; z==2 writes V^T to g_vt
    gemm_h<64, false><<<dim3(DM / 128, (NB * SQ) / 64, 3), 128, GEMM_SMEM>>>(
        (const __half*)xp, (const __half*)wqp, (const __half*)wkp,
        (const __half*)wvp, qp, kp, nullptr);

    // 2) flash attention (fp16, heavy-first, f16x2 exp) — R12 best config
    attn_h<<<(SQ / 64) * NB * NH, 128, ATT_SMEM>>>();

    // 3) output projection (fp32 out)
    gemm_h<64, true><<<dim3(DM / 128, (NB * SQ) / 64, 1), 128, GEMM_SMEM>>>(
        (const __half*)ap, (const __half*)wop, (const __half*)wop,
        (const __half*)wop, out, out, out);
}